// round 2
// baseline (speedup 1.0000x reference)
#include <cuda_runtime.h>
#include <math.h>

#define NN 50000
#define EE 800000
#define D  64
#define GG 64
#define BN_EPS 1e-5f

// ---------------- device scratch (no allocation allowed) ----------------
// NOTE: these symbols are ONLY referenced from device code (by name or via
// compile-time template selection). Passing them from host code would pass
// the host shadow address — that was the Round-1 bug.
__device__ __align__(16) float g_deg [NN];
__device__ __align__(16) float g_dinv[NN];
__device__ __align__(16) float g_h1  [NN * D];   // h1 = x@W1
__device__ __align__(16) float g_agg [NN * D];   // layer-1 agg -> pre-BN -> activations
__device__ __align__(16) float g_h2  [NN * D];   // h2 = act@W2
__device__ float g_bnsum[D];
__device__ float g_bnsq [D];
__device__ float g_scale[D];
__device__ float g_shift[D];
__device__ __align__(16) float g_pool[GG * D];
__device__ float g_cnt [GG];

// ---------------- init: zero everything we accumulate into ----------------
__global__ void zero_kernel(float* __restrict__ out) {
    int i = blockIdx.x * blockDim.x + threadIdx.x;
    if (i < NN * D) { g_agg[i] = 0.f; out[i] = 0.f; }
    if (i < NN)      g_deg[i] = 0.f;
    if (i < GG * D)  g_pool[i] = 0.f;
    if (i < D)     { g_bnsum[i] = 0.f; g_bnsq[i] = 0.f; }
    if (i < GG)      g_cnt[i] = 0.f;
}

// ---------------- degree + dinv ----------------
__global__ void degree_kernel(const int* __restrict__ dst) {
    int e = blockIdx.x * blockDim.x + threadIdx.x;
    if (e < EE) atomicAdd(&g_deg[dst[e]], 1.0f);
}

__global__ void dinv_kernel() {
    int i = blockIdx.x * blockDim.x + threadIdx.x;
    if (i < NN) g_dinv[i] = rsqrtf(g_deg[i] + 1.0f);
}

// ---------------- GEMM: Y[NN,64] = X[NN,64] @ W[64,64] ----------------
// MODE 0: X = x (param),  Y = g_h1
// MODE 1: X = g_agg,      Y = g_h2
// 64x64 output tile per block, blockDim (16,16), 4x4 register blocking.
template<int MODE>
__global__ void gemm64_kernel(const float* __restrict__ Xp,
                              const float* __restrict__ W) {
    const float* __restrict__ X = (MODE == 0) ? Xp : (const float*)g_agg;
    float* __restrict__       Y = (MODE == 0) ? g_h1 : g_h2;

    __shared__ float sX[64][65];
    __shared__ __align__(16) float sW[64][64];
    int tid  = threadIdx.y * 16 + threadIdx.x;
    int row0 = blockIdx.x * 64;

    #pragma unroll
    for (int t = tid * 4; t < 4096; t += 1024) {
        *(float4*)(&sW[t >> 6][t & 63]) = *(const float4*)(W + t);
    }
    #pragma unroll
    for (int t = tid * 4; t < 4096; t += 1024) {
        int r = t >> 6, c = t & 63;
        float4 v = make_float4(0.f, 0.f, 0.f, 0.f);
        if (row0 + r < NN) v = *(const float4*)(X + (size_t)(row0 + r) * D + c);
        sX[r][c] = v.x; sX[r][c + 1] = v.y; sX[r][c + 2] = v.z; sX[r][c + 3] = v.w;
    }
    __syncthreads();

    float acc[4][4] = {};
    int c0 = threadIdx.x * 4, r0 = threadIdx.y * 4;
    #pragma unroll 16
    for (int k = 0; k < 64; k++) {
        float4 w = *(const float4*)(&sW[k][c0]);
        #pragma unroll
        for (int r = 0; r < 4; r++) {
            float xv = sX[r0 + r][k];
            acc[r][0] += xv * w.x; acc[r][1] += xv * w.y;
            acc[r][2] += xv * w.z; acc[r][3] += xv * w.w;
        }
    }
    #pragma unroll
    for (int r = 0; r < 4; r++) {
        int row = row0 + r0 + r;
        if (row < NN)
            *(float4*)(Y + (size_t)row * D + c0) =
                make_float4(acc[r][0], acc[r][1], acc[r][2], acc[r][3]);
    }
}

// ---------------- edge scatter: agg[dst] += dinv[src]*dinv[dst]*h[src] ----------------
// MODE 0: h = g_h1, agg = g_agg.   MODE 1: h = g_h2, agg = outp (d_out).
// 16 threads per edge, each handles one float4 (vectorized red.global).
template<int MODE>
__global__ void scatter_kernel(const int* __restrict__ src,
                               const int* __restrict__ dst,
                               float* __restrict__ outp) {
    const float* __restrict__ h   = (MODE == 0) ? g_h1 : g_h2;
    float* __restrict__       agg = (MODE == 0) ? g_agg : outp;

    long long gt = (long long)blockIdx.x * blockDim.x + threadIdx.x;
    int e = (int)(gt >> 4);
    int q = (int)(gt & 15);
    if (e >= EE) return;
    int s = src[e], d = dst[e];
    float c = g_dinv[s] * g_dinv[d];
    float4 v = ((const float4*)h)[(size_t)s * 16 + q];
    v.x *= c; v.y *= c; v.z *= c; v.w *= c;
    atomicAdd(((float4*)agg) + (size_t)d * 16 + q, v);
}

// ---------------- combine (+ BN stats for layer 1), in place ----------------
// MODE 0: hb = g_agg, h = g_h1, computes BN stats.
// MODE 1: hb = outp,  h = g_h2, no stats.
// grid*block must be a multiple of 64 so each thread owns one column j.
template<int MODE>
__global__ void combine_stats_kernel(float* __restrict__ outp,
                                     const float* __restrict__ bias) {
    float* __restrict__       hb = (MODE == 0) ? g_agg : outp;
    const float* __restrict__ h  = (MODE == 0) ? g_h1 : g_h2;

    int tid    = blockIdx.x * blockDim.x + threadIdx.x;
    int stride = gridDim.x * blockDim.x;
    int j  = tid & 63;
    float bj = bias[j];
    float sum = 0.f, sq = 0.f;
    for (int idx = tid; idx < NN * D; idx += stride) {
        int i = idx >> 6;
        float di = g_dinv[i];
        float v = hb[idx] + h[idx] * di * di + bj;
        hb[idx] = v;
        sum += v; sq += v * v;
    }
    if (MODE != 0) return;
    __shared__ float s_sum[256], s_sq[256];
    s_sum[threadIdx.x] = sum; s_sq[threadIdx.x] = sq;
    __syncthreads();
    if (threadIdx.x < 64) {
        float ts = s_sum[threadIdx.x] + s_sum[threadIdx.x + 64] +
                   s_sum[threadIdx.x + 128] + s_sum[threadIdx.x + 192];
        float tq = s_sq[threadIdx.x] + s_sq[threadIdx.x + 64] +
                   s_sq[threadIdx.x + 128] + s_sq[threadIdx.x + 192];
        atomicAdd(&g_bnsum[threadIdx.x], ts);
        atomicAdd(&g_bnsq[threadIdx.x], tq);
    }
}

__global__ void bn_finalize_kernel(const float* __restrict__ gamma,
                                   const float* __restrict__ beta) {
    int j = threadIdx.x;
    if (j >= D) return;
    float inv_n = 1.0f / (float)NN;
    float mu  = g_bnsum[j] * inv_n;
    float var = g_bnsq[j] * inv_n - mu * mu;
    float sc  = gamma[j] * rsqrtf(var + BN_EPS);
    g_scale[j] = sc;
    g_shift[j] = beta[j] - mu * sc;
}

__global__ void bn_elu_kernel() {
    int idx = blockIdx.x * blockDim.x + threadIdx.x;
    if (idx >= NN * D) return;
    int j = idx & 63;
    float v = g_agg[idx] * g_scale[j] + g_shift[j];
    g_agg[idx] = (v > 0.f) ? v : (expf(v) - 1.0f);
}

// ---------------- global mean pool ----------------
__global__ void pool_kernel(const float* __restrict__ out,
                            const int* __restrict__ batch) {
    long long gt = (long long)blockIdx.x * blockDim.x + threadIdx.x;
    int i = (int)(gt >> 4);
    int q = (int)(gt & 15);
    if (i >= NN) return;
    int g = batch[i];
    if (q == 0) atomicAdd(&g_cnt[g], 1.0f);
    float4 v = ((const float4*)out)[(size_t)i * 16 + q];
    atomicAdd(((float4*)g_pool) + (size_t)g * 16 + q, v);
}

__global__ void pool_div_kernel(float* __restrict__ rep) {
    int t = blockIdx.x * blockDim.x + threadIdx.x;
    if (t >= GG * D) return;
    int g = t >> 6;
    rep[t] = g_pool[t] / fmaxf(g_cnt[g], 1.0f);
}

// ---------------- launch ----------------
extern "C" void kernel_launch(void* const* d_in, const int* in_sizes, int n_in,
                              void* d_out, int out_size) {
    const float* x     = (const float*)d_in[0];
    const int*   ei    = (const int*)  d_in[1];
    const int*   batch = (const int*)  d_in[2];
    const float* W1    = (const float*)d_in[3];
    const float* b1    = (const float*)d_in[4];
    const float* gamma = (const float*)d_in[5];
    const float* beta  = (const float*)d_in[6];
    const float* W2    = (const float*)d_in[7];
    const float* b2    = (const float*)d_in[8];
    float* out = (float*)d_out;                 // [NN*D] node out, then [GG*D] graph rep
    const int* src = ei;
    const int* dst = ei + EE;

    const int TPB = 256;
    int nd_blocks   = (NN * D + TPB - 1) / TPB;        // 12500
    int edge_blocks = (EE + TPB - 1) / TPB;            // 3125
    int node_blocks = (NN + TPB - 1) / TPB;
    int sc_blocks   = (int)(((long long)EE * 16 + TPB - 1) / TPB);  // 50000
    int gemm_blocks = (NN + 63) / 64;                  // 782
    int pool_blocks = (int)(((long long)NN * 16 + TPB - 1) / TPB);

    // 0) zero accumulators (g_agg, g_deg, bn stats, pool, d_out used as agg2)
    zero_kernel<<<nd_blocks, TPB>>>(out);
    // 1) degrees & dinv
    degree_kernel<<<edge_blocks, TPB>>>(dst);
    dinv_kernel<<<node_blocks, TPB>>>();
    // 2) h1 = x @ W1
    gemm64_kernel<0><<<gemm_blocks, dim3(16, 16)>>>(x, W1);
    // 3) agg1[dst] += c * h1[src]
    scatter_kernel<0><<<sc_blocks, TPB>>>(src, dst, out);
    // 4) pre-BN h = agg1 + h1*dinv^2 + b1 (in place in g_agg) + column stats
    combine_stats_kernel<0><<<1024, 256>>>(out, b1);
    bn_finalize_kernel<<<1, 64>>>(gamma, beta);
    // 5) BN + ELU in place
    bn_elu_kernel<<<nd_blocks, TPB>>>();
    // 6) h2 = act @ W2
    gemm64_kernel<1><<<gemm_blocks, dim3(16, 16)>>>(x, W2);
    // 7) agg2 (in d_out) += c * h2[src]
    scatter_kernel<1><<<sc_blocks, TPB>>>(src, dst, out);
    // 8) out = agg2 + h2*dinv^2 + b2 (in place in d_out)
    combine_stats_kernel<1><<<1024, 256>>>(out, b2);
    // 9) global mean pool -> d_out[NN*D ...]
    pool_kernel<<<pool_blocks, TPB>>>(out, batch);
    pool_div_kernel<<<(GG * D + TPB - 1) / TPB, TPB>>>(out + (size_t)NN * D);
}

// round 3
// speedup vs baseline: 1.1930x; 1.1930x over previous
#include <cuda_runtime.h>
#include <math.h>

#define NN 50000
#define EE 800000
#define D  64
#define GG 64
#define BN_EPS 1e-5f
#define SCAN_BLOCKS 196   // ceil(50000/256)

// ---------------- device scratch (device-code access only) ----------------
__device__ int   g_degi  [NN];
__device__ float g_dinv  [NN];
__device__ int   g_rowptr[NN];
__device__ int   g_cursor[NN];
__device__ int   g_blocksum[256];
__device__ int   g_blockoff[256];
__device__ int   g_csr_src [EE];
__device__ float g_csr_coef[EE];
__device__ __align__(16) float g_h1 [NN * D];   // h1 = x@W1
__device__ __align__(16) float g_agg[NN * D];   // pre-BN layer-1 result
__device__ __align__(16) float g_h2 [NN * D];   // h2 = act@W2
__device__ float g_bnsum[D];
__device__ float g_bnsq [D];
__device__ float g_scale[D];
__device__ float g_shift[D];
__device__ __align__(16) float g_pool[GG * D];
__device__ float g_cnt [GG];

// ---------------- zero the (small) accumulators ----------------
__global__ void zero_kernel() {
    int i = blockIdx.x * blockDim.x + threadIdx.x;
    if (i < NN)     g_degi[i] = 0;
    if (i < GG * D) g_pool[i] = 0.f;
    if (i < D)    { g_bnsum[i] = 0.f; g_bnsq[i] = 0.f; }
    if (i < GG)     g_cnt[i] = 0.f;
}

// ---------------- degree + dinv ----------------
__global__ void degree_kernel(const int* __restrict__ dst) {
    int e = blockIdx.x * blockDim.x + threadIdx.x;
    if (e < EE) atomicAdd(&g_degi[dst[e]], 1);
}

__global__ void dinv_kernel() {
    int i = blockIdx.x * blockDim.x + threadIdx.x;
    if (i < NN) g_dinv[i] = rsqrtf((float)g_degi[i] + 1.0f);
}

// ---------------- 3-phase exclusive scan of degrees -> rowptr ----------------
__global__ void scan1_kernel() {              // per-block sums
    __shared__ int s[256];
    int idx = blockIdx.x * 256 + threadIdx.x;
    s[threadIdx.x] = (idx < NN) ? g_degi[idx] : 0;
    __syncthreads();
    for (int o = 128; o > 0; o >>= 1) {
        if (threadIdx.x < o) s[threadIdx.x] += s[threadIdx.x + o];
        __syncthreads();
    }
    if (threadIdx.x == 0) g_blocksum[blockIdx.x] = s[0];
}

__global__ void scan2_kernel() {              // scan the block sums (1 block)
    __shared__ int s[256];
    int t = threadIdx.x;
    int v = (t < SCAN_BLOCKS) ? g_blocksum[t] : 0;
    s[t] = v;
    __syncthreads();
    for (int o = 1; o < 256; o <<= 1) {
        int add = (t >= o) ? s[t - o] : 0;
        __syncthreads();
        s[t] += add;
        __syncthreads();
    }
    g_blockoff[t] = s[t] - v;                 // exclusive
}

__global__ void scan3_kernel() {              // per-element exclusive scan + offset
    __shared__ int s[256];
    int t = threadIdx.x;
    int idx = blockIdx.x * 256 + t;
    int v = (idx < NN) ? g_degi[idx] : 0;
    s[t] = v;
    __syncthreads();
    for (int o = 1; o < 256; o <<= 1) {
        int add = (t >= o) ? s[t - o] : 0;
        __syncthreads();
        s[t] += add;
        __syncthreads();
    }
    if (idx < NN) {
        int rp = g_blockoff[blockIdx.x] + s[t] - v;
        g_rowptr[idx] = rp;
        g_cursor[idx] = rp;
    }
}

// ---------------- CSR fill: group (src, coef) by dst ----------------
__global__ void csr_fill_kernel(const int* __restrict__ src,
                                const int* __restrict__ dst) {
    int e = blockIdx.x * blockDim.x + threadIdx.x;
    if (e >= EE) return;
    int s = src[e], d = dst[e];
    int pos = atomicAdd(&g_cursor[d], 1);
    g_csr_src[pos]  = s;
    g_csr_coef[pos] = g_dinv[s] * g_dinv[d];
}

// ---------------- GEMM: Y[NN,64] = X[NN,64] @ W[64,64] ----------------
// MODE 0: X = x (param), Y = g_h1.
// MODE 1: X = elu(bn(g_agg)) applied on load, Y = g_h2.
template<int MODE>
__global__ void gemm64_kernel(const float* __restrict__ Xp,
                              const float* __restrict__ W) {
    const float* __restrict__ X = (MODE == 0) ? Xp : (const float*)g_agg;
    float* __restrict__       Y = (MODE == 0) ? g_h1 : g_h2;

    __shared__ float sX[64][65];
    __shared__ __align__(16) float sW[64][64];
    int tid  = threadIdx.y * 16 + threadIdx.x;
    int row0 = blockIdx.x * 64;

    #pragma unroll
    for (int t = tid * 4; t < 4096; t += 1024) {
        *(float4*)(&sW[t >> 6][t & 63]) = *(const float4*)(W + t);
    }
    #pragma unroll
    for (int t = tid * 4; t < 4096; t += 1024) {
        int r = t >> 6, c = t & 63;
        float4 v = make_float4(0.f, 0.f, 0.f, 0.f);
        if (row0 + r < NN) v = *(const float4*)(X + (size_t)(row0 + r) * D + c);
        if (MODE == 1) {
            // fused BatchNorm + ELU on the activation load
            v.x = v.x * g_scale[c]     + g_shift[c];
            v.y = v.y * g_scale[c + 1] + g_shift[c + 1];
            v.z = v.z * g_scale[c + 2] + g_shift[c + 2];
            v.w = v.w * g_scale[c + 3] + g_shift[c + 3];
            v.x = (v.x > 0.f) ? v.x : (__expf(v.x) - 1.0f);
            v.y = (v.y > 0.f) ? v.y : (__expf(v.y) - 1.0f);
            v.z = (v.z > 0.f) ? v.z : (__expf(v.z) - 1.0f);
            v.w = (v.w > 0.f) ? v.w : (__expf(v.w) - 1.0f);
        }
        sX[r][c] = v.x; sX[r][c + 1] = v.y; sX[r][c + 2] = v.z; sX[r][c + 3] = v.w;
    }
    __syncthreads();

    float acc[4][4] = {};
    int c0 = threadIdx.x * 4, r0 = threadIdx.y * 4;
    #pragma unroll 16
    for (int k = 0; k < 64; k++) {
        float4 w = *(const float4*)(&sW[k][c0]);
        #pragma unroll
        for (int r = 0; r < 4; r++) {
            float xv = sX[r0 + r][k];
            acc[r][0] += xv * w.x; acc[r][1] += xv * w.y;
            acc[r][2] += xv * w.z; acc[r][3] += xv * w.w;
        }
    }
    #pragma unroll
    for (int r = 0; r < 4; r++) {
        int row = row0 + r0 + r;
        if (row < NN)
            *(float4*)(Y + (size_t)row * D + c0) =
                make_float4(acc[r][0], acc[r][1], acc[r][2], acc[r][3]);
    }
}

// ---------------- gather aggregation: one warp per node ----------------
// out[n] = sum_{e in CSR[n]} coef[e]*h[src[e]] + dinv[n]^2*h[n] + bias
// MODE 0: h=g_h1, write g_agg, accumulate BN stats.
// MODE 1: h=g_h2, write outp,  fused global-mean-pool atomics.
template<int MODE>
__global__ void aggregate_kernel(float* __restrict__ outp,
                                 const float* __restrict__ bias,
                                 const int* __restrict__ batch) {
    const float* __restrict__ h = (MODE == 0) ? g_h1 : g_h2;
    float* __restrict__ dstbuf  = (MODE == 0) ? g_agg : outp;

    int gwarp = (blockIdx.x * blockDim.x + threadIdx.x) >> 5;
    int lane  = threadIdx.x & 31;
    // grid sized so gwarp < NN always (6250 blocks * 8 warps = 50000)
    int n  = gwarp;
    int e0 = g_rowptr[n];
    int e1 = e0 + g_degi[n];

    float2 acc = make_float2(0.f, 0.f);
    for (int base = e0; base < e1; base += 32) {
        int m = e1 - base; if (m > 32) m = 32;
        int   s_l = 0;
        float c_l = 0.f;
        if (lane < m) { s_l = g_csr_src[base + lane]; c_l = g_csr_coef[base + lane]; }
        for (int j = 0; j < m; j++) {
            int   s = __shfl_sync(0xffffffffu, s_l, j);
            float c = __shfl_sync(0xffffffffu, c_l, j);
            float2 v = ((const float2*)h)[(size_t)s * 32 + lane];
            acc.x = fmaf(c, v.x, acc.x);
            acc.y = fmaf(c, v.y, acc.y);
        }
    }
    // self-loop + bias
    float di = g_dinv[n];
    float cs = di * di;
    float2 hv = ((const float2*)h)[(size_t)n * 32 + lane];
    float2 bv = ((const float2*)bias)[lane];
    acc.x = fmaf(cs, hv.x, acc.x) + bv.x;
    acc.y = fmaf(cs, hv.y, acc.y) + bv.y;

    ((float2*)dstbuf)[(size_t)n * 32 + lane] = acc;

    if (MODE == 0) {
        // BN statistics: block-level smem reduction, one global atomic per col
        __shared__ float s_sum[64], s_sq[64];
        if (threadIdx.x < 64) { s_sum[threadIdx.x] = 0.f; s_sq[threadIdx.x] = 0.f; }
        __syncthreads();
        atomicAdd(&s_sum[2 * lane],     acc.x);
        atomicAdd(&s_sum[2 * lane + 1], acc.y);
        atomicAdd(&s_sq [2 * lane],     acc.x * acc.x);
        atomicAdd(&s_sq [2 * lane + 1], acc.y * acc.y);
        __syncthreads();
        if (threadIdx.x < 64) {
            atomicAdd(&g_bnsum[threadIdx.x], s_sum[threadIdx.x]);
            atomicAdd(&g_bnsq [threadIdx.x], s_sq [threadIdx.x]);
        }
    } else {
        // fused global mean pool
        int g = batch[n];
        if (lane == 0) atomicAdd(&g_cnt[g], 1.0f);
        atomicAdd(((float2*)g_pool) + (size_t)g * 32 + lane, acc);
    }
}

__global__ void bn_finalize_kernel(const float* __restrict__ gamma,
                                   const float* __restrict__ beta) {
    int j = threadIdx.x;
    if (j >= D) return;
    float inv_n = 1.0f / (float)NN;
    float mu  = g_bnsum[j] * inv_n;
    float var = g_bnsq[j] * inv_n - mu * mu;
    float sc  = gamma[j] * rsqrtf(var + BN_EPS);
    g_scale[j] = sc;
    g_shift[j] = beta[j] - mu * sc;
}

__global__ void pool_div_kernel(float* __restrict__ rep) {
    int t = blockIdx.x * blockDim.x + threadIdx.x;
    if (t >= GG * D) return;
    int g = t >> 6;
    rep[t] = g_pool[t] / fmaxf(g_cnt[g], 1.0f);
}

// ---------------- launch ----------------
extern "C" void kernel_launch(void* const* d_in, const int* in_sizes, int n_in,
                              void* d_out, int out_size) {
    const float* x     = (const float*)d_in[0];
    const int*   ei    = (const int*)  d_in[1];
    const int*   batch = (const int*)  d_in[2];
    const float* W1    = (const float*)d_in[3];
    const float* b1    = (const float*)d_in[4];
    const float* gamma = (const float*)d_in[5];
    const float* beta  = (const float*)d_in[6];
    const float* W2    = (const float*)d_in[7];
    const float* b2    = (const float*)d_in[8];
    float* out = (float*)d_out;                 // [NN*D] node out, then [GG*D] graph rep
    const int* src = ei;
    const int* dst = ei + EE;

    const int TPB = 256;
    int edge_blocks = (EE + TPB - 1) / TPB;            // 3125
    int node_blocks = (NN + TPB - 1) / TPB;            // 196
    int gemm_blocks = (NN + 63) / 64;                  // 782
    int agg_blocks  = NN / 8;                          // 6250 (8 warps/block, warp per node)

    zero_kernel<<<node_blocks, TPB>>>();
    degree_kernel<<<edge_blocks, TPB>>>(dst);
    dinv_kernel<<<node_blocks, TPB>>>();
    // exclusive scan -> rowptr/cursor
    scan1_kernel<<<SCAN_BLOCKS, 256>>>();
    scan2_kernel<<<1, 256>>>();
    scan3_kernel<<<SCAN_BLOCKS, 256>>>();
    csr_fill_kernel<<<edge_blocks, TPB>>>(src, dst);
    // layer 1
    gemm64_kernel<0><<<gemm_blocks, dim3(16, 16)>>>(x, W1);
    aggregate_kernel<0><<<agg_blocks, TPB>>>(out, b1, batch);
    bn_finalize_kernel<<<1, 64>>>(gamma, beta);
    // layer 2 (BN+ELU fused into gemm X load)
    gemm64_kernel<1><<<gemm_blocks, dim3(16, 16)>>>(x, W2);
    aggregate_kernel<1><<<agg_blocks, TPB>>>(out, b2, batch);
    // graph readout
    pool_div_kernel<<<(GG * D + TPB - 1) / TPB, TPB>>>(out + (size_t)NN * D);
}